// round 11
// baseline (speedup 1.0000x reference)
#include <cuda_runtime.h>
#include <cstdint>

typedef unsigned long long ull;

#define NBLK 128

// ---------------- scratch (no mallocs allowed) ----------------
__device__ float g_keys[64 * 256 * 1024];             // memory @ W_mem          64MB
__device__ float g_MW[64 * 256 * 1024];               // memory @ W_attn[1024:]  64MB
__device__ float g_attn_all[(size_t)64 * 256 * 1024]; // attn outputs            64MB
__device__ float g_Wz[(size_t)3072 * 4096];           // gate-interleaved [Wl;Ul] 48MB
__device__ float g_Zx[(size_t)64 * 256 * 4096];       // dec @ Wz_top + bias    256MB
__device__ float g_xat[1024 * 64];                    // attn transposed [u][b]
__device__ float g_hT[2][1024 * 64];                  // h transposed, double buffered
__device__ float g_c[64 * 1024];
__device__ float g_q2[64 * 2048];                     // [q | h@Wa_top]
__device__ float g_scores[64 * 256];
__device__ unsigned g_cntg[8 * 32];                   // padded group counters
__device__ unsigned g_cntr;                           // root counter
__device__ volatile unsigned g_gen;
__device__ unsigned g_pcnt[64];
__device__ volatile unsigned g_pgen[64];

// ---------------- helpers ----------------
__device__ __forceinline__ ull pack2dup(float x) {
    ull r;
    asm("mov.b64 %0, {%1, %1};" : "=l"(r) : "f"(x));
    return r;
}
__device__ __forceinline__ float2 unpack2(ull v) {
    float2 r;
    asm("mov.b64 {%0, %1}, %2;" : "=f"(r.x), "=f"(r.y) : "l"(v));
    return r;
}
__device__ __forceinline__ void fma2(ull& acc, ull a, ull b) {
    asm("fma.rn.f32x2 %0, %1, %2, %0;" : "+l"(acc) : "l"(a), "l"(b));
}
__device__ __forceinline__ ull add2(ull a, ull b) {
    ull r;
    asm("add.rn.f32x2 %0, %1, %2;" : "=l"(r) : "l"(a), "l"(b));
    return r;
}
__device__ __forceinline__ float tanh_ap(float x) {
    float y;
    asm("tanh.approx.f32 %0, %1;" : "=f"(y) : "f"(x));
    return y;
}
__device__ __forceinline__ float sigf(float x) { return 1.0f / (1.0f + __expf(-x)); }

__device__ __forceinline__ unsigned sptr(const void* p) {
    return (unsigned)__cvta_generic_to_shared(p);
}
__device__ __forceinline__ unsigned f2tf32(float f) {
    unsigned u;
    asm("cvt.rna.tf32.f32 %0, %1;" : "=r"(u) : "f"(f));
    return u;
}
#define CPA16(d, s) asm volatile("cp.async.cg.shared.global [%0], [%1], 16;" :: "r"(d), "l"(s))
#define CPA16P(d, s, pol) \
    asm volatile("cp.async.cg.shared.global.L2::cache_hint [%0], [%1], 16, %2;" \
                 :: "r"(d), "l"(s), "l"(pol))
#define CPC()       asm volatile("cp.async.commit_group;")
#define CPW(n)      asm volatile("cp.async.wait_group %0;" :: "n"(n))

__device__ __forceinline__ ull evict_first_policy() {
    ull p;
    asm("createpolicy.fractional.L2::evict_first.b64 %0, 1.0;" : "=l"(p));
    return p;
}

// ---------------- software grid barrier (2-level arrival, monotonic) --------
__device__ __forceinline__ void gsync(int bid) {
    __syncthreads();
    if (threadIdx.x == 0) {
        unsigned g = g_gen;
        __threadfence();
        int grp = (bid >> 4) * 32;
        if ((atomicAdd(&g_cntg[grp], 1u) & 15u) == 15u) {
            if ((atomicAdd(&g_cntr, 1u) & 7u) == 7u) {
                __threadfence();
                g_gen = g + 1;
            }
        }
        if (g_gen == g) {
            do { __nanosleep(32); } while (g_gen == g);
        }
        __threadfence();
    }
    __syncthreads();
}

// ---------------- block-pair barrier (blocks 2p, 2p+1), monotonic ----------
__device__ __forceinline__ void psync(int pair) {
    __syncthreads();
    if (threadIdx.x == 0) {
        unsigned g = g_pgen[pair];
        __threadfence();
        if (atomicAdd(&g_pcnt[pair], 1u) & 1u) {
            __threadfence();
            g_pgen[pair] = g + 1;
        } else {
            while (g_pgen[pair] == g) {}
        }
        __threadfence();
    }
    __syncthreads();
}

// ---------------- tf32 tensor-core GEMM: C[M,N] = A[M,K]@B[K,N] (+bias) -----
// block tile 128x64, BK=32; 8 warps of 64x16; M%128==0, N%64==0, K%32==0
// perm!=0: write column n to n' = (n&1023)*4 + (n>>10)  (gate interleave)
__global__ __launch_bounds__(256, 2) void gemm_tf32(
    const float* __restrict__ A, const float* __restrict__ Bm,
    const float* __restrict__ bias, float* __restrict__ C, int M, int N, int K,
    int perm)
{
    __shared__ __align__(16) unsigned As[32][136];  // [k][m] tf32 bits
    __shared__ __align__(16) unsigned Bs[32][72];   // [k][n]

    const int tid = threadIdx.x;
    const int w = tid >> 5, lane = tid & 31;
    const int g = lane >> 2, tg = lane & 3;
    const int wm = (w & 1) * 64, wn = (w >> 1) * 16;

    const int m_a = tid >> 1;
    const int ka0 = (tid & 1) * 16;
    const int k_b = tid >> 3;
    const int n_b = (tid & 7) * 8;

    const float* Ap = A + (size_t)(blockIdx.y * 128 + m_a) * K + ka0;
    const float* Bp = Bm + (size_t)k_b * N + blockIdx.x * 64 + n_b;

    float acc[4][2][4];
#pragma unroll
    for (int mt = 0; mt < 4; ++mt)
#pragma unroll
        for (int nt = 0; nt < 2; ++nt)
#pragma unroll
            for (int i = 0; i < 4; ++i) acc[mt][nt][i] = 0.f;

    float4 ra[4], rb[2];
#pragma unroll
    for (int e = 0; e < 4; ++e) ra[e] = *(const float4*)(Ap + e * 4);
    rb[0] = *(const float4*)(Bp);
    rb[1] = *(const float4*)(Bp + 4);

    for (int k0 = 0; k0 < K; k0 += 32) {
        if (k0) __syncthreads();
#pragma unroll
        for (int e = 0; e < 4; ++e) {
            As[ka0 + e * 4 + 0][m_a] = f2tf32(ra[e].x);
            As[ka0 + e * 4 + 1][m_a] = f2tf32(ra[e].y);
            As[ka0 + e * 4 + 2][m_a] = f2tf32(ra[e].z);
            As[ka0 + e * 4 + 3][m_a] = f2tf32(ra[e].w);
        }
#pragma unroll
        for (int e = 0; e < 2; ++e) {
            uint4 t;
            t.x = f2tf32(rb[e].x);
            t.y = f2tf32(rb[e].y);
            t.z = f2tf32(rb[e].z);
            t.w = f2tf32(rb[e].w);
            *(uint4*)&Bs[k_b][n_b + e * 4] = t;
        }
        __syncthreads();
        if (k0 + 32 < K) {
#pragma unroll
            for (int e = 0; e < 4; ++e)
                ra[e] = *(const float4*)(Ap + k0 + 32 + e * 4);
            rb[0] = *(const float4*)(Bp + (size_t)(k0 + 32) * N);
            rb[1] = *(const float4*)(Bp + (size_t)(k0 + 32) * N + 4);
        }
#pragma unroll
        for (int ks = 0; ks < 4; ++ks) {
            const int kk = ks * 8;
            unsigned af[4][4], bf[2][2];
#pragma unroll
            for (int mt = 0; mt < 4; ++mt) {
                int mb = wm + mt * 16 + g;
                af[mt][0] = As[kk + tg][mb];
                af[mt][1] = As[kk + tg][mb + 8];
                af[mt][2] = As[kk + tg + 4][mb];
                af[mt][3] = As[kk + tg + 4][mb + 8];
            }
#pragma unroll
            for (int nt = 0; nt < 2; ++nt) {
                int nb = wn + nt * 8 + g;
                bf[nt][0] = Bs[kk + tg][nb];
                bf[nt][1] = Bs[kk + tg + 4][nb];
            }
#pragma unroll
            for (int mt = 0; mt < 4; ++mt)
#pragma unroll
                for (int nt = 0; nt < 2; ++nt) {
                    asm volatile(
                        "mma.sync.aligned.m16n8k8.row.col.f32.tf32.tf32.f32 "
                        "{%0,%1,%2,%3}, {%4,%5,%6,%7}, {%8,%9}, {%0,%1,%2,%3};"
                        : "+f"(acc[mt][nt][0]), "+f"(acc[mt][nt][1]),
                          "+f"(acc[mt][nt][2]), "+f"(acc[mt][nt][3])
                        : "r"(af[mt][0]), "r"(af[mt][1]), "r"(af[mt][2]),
                          "r"(af[mt][3]), "r"(bf[nt][0]), "r"(bf[nt][1]));
                }
        }
    }

#pragma unroll
    for (int mt = 0; mt < 4; ++mt) {
#pragma unroll
        for (int nt = 0; nt < 2; ++nt) {
            int m = blockIdx.y * 128 + wm + mt * 16 + g;
            int n = blockIdx.x * 64 + wn + nt * 8 + 2 * tg;
            float c0 = acc[mt][nt][0], c1 = acc[mt][nt][1];
            float c2 = acc[mt][nt][2], c3 = acc[mt][nt][3];
            if (bias) {
                float b0 = bias[n], b1 = bias[n + 1];
                c0 += b0; c1 += b1; c2 += b0; c3 += b1;
            }
            if (perm) {
                int np0 = (n & 1023) * 4 + (n >> 10);
                int np1 = ((n + 1) & 1023) * 4 + ((n + 1) >> 10);
                C[(size_t)m * N + np0] = c0;
                C[(size_t)m * N + np1] = c1;
                C[(size_t)(m + 8) * N + np0] = c2;
                C[(size_t)(m + 8) * N + np1] = c3;
            } else {
                *(float2*)(C + (size_t)m * N + n) = make_float2(c0, c1);
                *(float2*)(C + (size_t)(m + 8) * N + n) = make_float2(c2, c3);
            }
        }
    }
}

// ---------------- persistent megakernel: all 256 decoder steps ----------------
// dynamic smem (floats):
//  actb[2][8192] wb[2][4096] zs[4224 ull] qv[1024] vv[1024] red[256] ps[256]
#define SMEM_FLOATS (16384 + 8192 + 8448 + 1024 + 1024 + 256 + 256)
#define SMEM_BYTES  (SMEM_FLOATS * 4)

__global__ __launch_bounds__(256, 1) void mega(
    const float* __restrict__ h0, const float* __restrict__ c0,
    const float* __restrict__ Wl, const float* __restrict__ Ul,
    const float* __restrict__ Wq, const float* __restrict__ Wa,
    const float* __restrict__ va, const int* __restrict__ mlen)
{
    extern __shared__ __align__(16) float smem[];
    float* actb = smem;               // 2 x 8192
    float* wb   = smem + 16384;       // 2 x 4096
    ull*   zs   = (ull*)(smem + 24576);
    float* qv   = smem + 24576 + 8448;
    float* vv   = qv + 1024;
    float* red  = vv + 1024;
    float* ps   = red + 256;

    const int tid = threadIdx.x, bid = blockIdx.x;
    const int w = tid >> 5, lane = tid & 31;
    const unsigned actbu = sptr(actb), wbu = sptr(wb);
    const ull epol = evict_first_policy();

    // init: weight reorder W'[k][u*4+g] = [Wl;Ul][k][g*1024+u]
    for (size_t idx = (size_t)bid * 256 + tid; idx < (size_t)3072 * 4096;
         idx += (size_t)NBLK * 256) {
        int k = (int)(idx >> 12), cp = (int)(idx & 4095);
        int u = cp >> 2, gg = cp & 3;
        g_Wz[idx] = (k < 2048) ? Wl[(size_t)k * 4096 + gg * 1024 + u]
                               : Ul[(size_t)(k - 2048) * 4096 + gg * 1024 + u];
    }
    // init state (transposed)
    for (int i = bid * 256 + tid; i < 64 * 1024; i += NBLK * 256) {
        int b = i >> 10, u = i & 1023;
        g_hT[1][u * 64 + b] = h0[i];
        g_c[i] = c0[i];
        g_xat[u * 64 + b] = 0.f;   // attn_0 = 0
    }
    for (int i = tid; i < 1024; i += 256) vv[i] = va[i];

    // role constants
    const int q_cg = bid >> 1, q_bh = bid & 1;
    const float* q_wb = (q_cg < 32) ? (Wq + q_cg * 32 + lane)
                                    : (Wa + (q_cg - 32) * 32 + lane);
    const int sc_b = bid >> 1;
    const int sc_half = bid & 1;
    const int s_len = mlen[sc_b];

    gsync(bid);

    // prefetch Z weight chunk 0 (step-invariant)
    {
        const float* wsrc = g_Wz + (size_t)1024 * 4096 + bid * 32;
#pragma unroll
        for (int i = 0; i < 4; ++i) {
            int f = i * 256 + tid;
            int kk = f >> 3, j = f & 7;
            CPA16P(wbu + f * 16, wsrc + (size_t)kk * 4096 + j * 4, epol);
        }
        CPC();
    }

    for (int t = 0; t < 256; ++t) {
        const float* hTprev = g_hT[(t & 1) ^ 1];
        float* hTcur = g_hT[t & 1];

        // ===== Z: z = Zx[t] + [attn|h] @ Wz_bot ============================
        // hoist Zx epilogue loads (depend only on t)
        float4 zxr[2];
#pragma unroll
        for (int r = 0; r < 2; ++r) {
            int e = r * 256 + tid;
            int b = e >> 3, ul = e & 7;
            zxr[r] = __ldcs((const float4*)(
                g_Zx + ((size_t)b * 256 + t) * 4096 + (bid * 8 + ul) * 4));
        }
        ull acc[32];
#pragma unroll
        for (int p = 0; p < 32; ++p) acc[p] = 0ull;

        // stage act chunk 0 (weights chunk 0 already committed pre-barrier)
        {
            const float* asrc = g_xat;
#pragma unroll
            for (int i = 0; i < 8; ++i) {
                int f = i * 256 + tid;
                CPA16(actbu + f * 16, asrc + f * 4);
            }
            CPC();
        }
        for (int c = 0; c < 16; ++c) {
            int cb = c & 1;
            if (c < 15) {
                int cn = c + 1, nb = cb ^ 1;
                const float* asrc = (cn < 8) ? (g_xat + cn * 8192)
                                             : (hTprev + (cn - 8) * 8192);
                unsigned au = actbu + nb * 32768;
#pragma unroll
                for (int i = 0; i < 8; ++i) {
                    int f = i * 256 + tid;
                    CPA16(au + f * 16, asrc + f * 4);
                }
                const float* wsrc =
                    g_Wz + (size_t)(1024 + cn * 128) * 4096 + bid * 32;
                unsigned wu = wbu + nb * 16384;
#pragma unroll
                for (int i = 0; i < 4; ++i) {
                    int f = i * 256 + tid;
                    int kk = f >> 3, j = f & 7;
                    CPA16P(wu + f * 16, wsrc + (size_t)kk * 4096 + j * 4, epol);
                }
                CPC();
                CPW(1);
            } else {
                CPW(0);
            }
            __syncthreads();
            const float* ab = actb + cb * 8192;
            const float* wp = wb + cb * 4096;
#pragma unroll
            for (int kk = 0; kk < 16; ++kk) {
                int k = w * 16 + kk;
                ull wv = pack2dup(wp[k * 32 + lane]);
                const ulonglong2* ar = (const ulonglong2*)(ab + k * 64);
#pragma unroll
                for (int p = 0; p < 16; ++p) {
                    ulonglong2 a2 = ar[p];
                    fma2(acc[2 * p], wv, a2.x);
                    fma2(acc[2 * p + 1], wv, a2.y);
                }
            }
            __syncthreads();
        }
        // tree-reduce 8 warps -> warp0
#define ZST(r)                                                            \
        { _Pragma("unroll") for (int p = 0; p < 32; ++p)                  \
            zs[((r) * 32 + lane) * 33 + p] = acc[p]; }
#define ZAD(r)                                                            \
        { _Pragma("unroll") for (int p = 0; p < 32; ++p)                  \
            acc[p] = add2(acc[p], zs[((r) * 32 + lane) * 33 + p]); }
        if (w >= 4) ZST(w - 4);
        __syncthreads();
        if (w < 4) ZAD(w);
        __syncthreads();
        if (w == 2 || w == 3) ZST(w - 2);
        __syncthreads();
        if (w < 2) ZAD(w);
        __syncthreads();
        if (w == 1) ZST(0);
        __syncthreads();
        if (w == 0) { ZAD(0); ZST(0); }
        __syncthreads();
        // gate epilogue
#pragma unroll
        for (int r = 0; r < 2; ++r) {
            int e = r * 256 + tid;
            int b = e >> 3, ul = e & 7;
            float4 zx = zxr[r];
            float z0 = ((const float*)(zs + (ul * 4 + 0) * 33))[b] + zx.x;
            float z1 = ((const float*)(zs + (ul * 4 + 1) * 33))[b] + zx.y;
            float z2 = ((const float*)(zs + (ul * 4 + 2) * 33))[b] + zx.z;
            float z3 = ((const float*)(zs + (ul * 4 + 3) * 33))[b] + zx.w;
            float ig = sigf(z0), fg = sigf(z1);
            float gg = tanhf(z2), og = sigf(z3);
            int ci = b * 1024 + bid * 8 + ul;
            float cc = fg * g_c[ci] + ig * gg;
            g_c[ci] = cc;
            hTcur[(bid * 8 + ul) * 64 + b] = og * tanhf(cc);
        }
        gsync(bid);

        // ===== Q: [q | h@Wa_top] = h @ [Wq | Wa_top] (staged, 4 chunks) ====
        ull qa[16];
#pragma unroll
        for (int p = 0; p < 16; ++p) qa[p] = 0ull;
        {
#pragma unroll
            for (int i = 0; i < 8; ++i) {
                int f = i * 256 + tid;
                int kl = f >> 3, bc = f & 7;
                CPA16(actbu + f * 16,
                      hTcur + ((size_t)kl * 64 + q_bh * 32 + bc * 4));
            }
            CPC();
        }
        for (int c = 0; c < 4; ++c) {
            int cb = c & 1;
            if (c < 3) {
                int cn = c + 1, nb = cb ^ 1;
                unsigned au = actbu + nb * 32768;
#pragma unroll
                for (int i = 0; i < 8; ++i) {
                    int f = i * 256 + tid;
                    int kl = f >> 3, bc = f & 7;
                    CPA16(au + f * 16,
                          hTcur + ((size_t)(cn * 256 + kl) * 64 + q_bh * 32 + bc * 4));
                }
                CPC();
                CPW(1);
            } else {
                CPW(0);
            }
            __syncthreads();
            const float* hb = actb + cb * 8192;
#pragma unroll
            for (int g = 0; g < 4; ++g) {
                float wr[8];
                const float* wpg = q_wb + (size_t)(c * 256 + w * 32 + g * 8) * 1024;
#pragma unroll
                for (int kk = 0; kk < 8; ++kk) wr[kk] = wpg[(size_t)kk * 1024];
#pragma unroll
                for (int kk = 0; kk < 8; ++kk) {
                    ull wv = pack2dup(wr[kk]);
                    const ulonglong2* ar =
                        (const ulonglong2*)(hb + (w * 32 + g * 8 + kk) * 32);
#pragma unroll
                    for (int p = 0; p < 8; ++p) {
                        ulonglong2 a2 = ar[p];
                        fma2(qa[2 * p], wv, a2.x);
                        fma2(qa[2 * p + 1], wv, a2.y);
                    }
                }
            }
            __syncthreads();
        }
#define QST(r)                                                            \
        { _Pragma("unroll") for (int p = 0; p < 16; ++p)                  \
            zs[((r) * 32 + lane) * 33 + p] = qa[p]; }
#define QAD(r)                                                            \
        { _Pragma("unroll") for (int p = 0; p < 16; ++p)                  \
            qa[p] = add2(qa[p], zs[((r) * 32 + lane) * 33 + p]); }
        if (w >= 4) QST(w - 4);
        __syncthreads();
        if (w < 4) QAD(w);
        __syncthreads();
        if (w == 2 || w == 3) QST(w - 2);
        __syncthreads();
        if (w < 2) QAD(w);
        __syncthreads();
        if (w == 1) QST(0);
        __syncthreads();
        if (w == 0) {
            QAD(0);
            int n = q_cg * 32 + lane;
#pragma unroll
            for (int p = 0; p < 16; ++p) {
                float2 v = unpack2(qa[p]);
                g_q2[(q_bh * 32 + 2 * p) * 2048 + n] = v.x;
                g_q2[(q_bh * 32 + 2 * p + 1) * 2048 + n] = v.y;
            }
        }
        gsync(bid);

        // ===== S: masked additive scores ===================================
        *(float4*)&qv[tid * 4] = *(const float4*)&g_q2[sc_b * 2048 + tid * 4];
        __syncthreads();
#pragma unroll
        for (int i = 0; i < 16; ++i) {
            int s = sc_half * 128 + w * 16 + i;
            float sv = -1e9f;
            if (s < s_len) {
                const float* kp = g_keys + ((size_t)sc_b * 256 + s) * 1024;
                float a = 0.f;
#pragma unroll
                for (int j = 0; j < 8; ++j) {
                    int u = lane * 4 + j * 128;
                    float4 kv = *(const float4*)(kp + u);
                    float4 qf = *(const float4*)(qv + u);
                    float4 vf = *(const float4*)(vv + u);
                    a += tanh_ap(kv.x + qf.x) * vf.x + tanh_ap(kv.y + qf.y) * vf.y
                       + tanh_ap(kv.z + qf.z) * vf.z + tanh_ap(kv.w + qf.w) * vf.w;
                }
#pragma unroll
                for (int off = 16; off; off >>= 1)
                    a += __shfl_xor_sync(0xffffffffu, a, off);
                sv = a;
            }
            if (lane == 0) g_scores[sc_b * 256 + s] = sv;
        }
        psync(sc_b);

        // ===== C: softmax + align@MW + hWa -> attn =========================
        {
            float mys = g_scores[sc_b * 256 + tid];
            red[tid] = mys;
            __syncthreads();
            for (int st = 128; st; st >>= 1) {
                if (tid < st) red[tid] = fmaxf(red[tid], red[tid + st]);
                __syncthreads();
            }
            float m = red[0];
            __syncthreads();
            float e = __expf(mys - m);   // masked rows underflow to exactly 0
            red[tid] = e;
            __syncthreads();
            for (int st = 128; st; st >>= 1) {
                if (tid < st) red[tid] += red[tid + st];
                __syncthreads();
            }
            float inv = 1.f / red[0];
            __syncthreads();
            ps[tid] = e * inv;
            __syncthreads();

            int len8 = (s_len + 7) & ~7;
            int u0 = sc_half * 512 + tid * 2;
            const float* mwp = g_MW + (size_t)sc_b * 256 * 1024 + u0;
            ull ca[8];
#pragma unroll
            for (int p = 0; p < 8; ++p) ca[p] = 0ull;
            for (int s = 0; s < len8; s += 8) {
#pragma unroll
                for (int j = 0; j < 8; ++j) {
                    ull mv = *(const ull*)(mwp + (size_t)(s + j) * 1024);
                    fma2(ca[j], pack2dup(ps[s + j]), mv);
                }
            }
            float o0 = 0.f, o1 = 0.f;
#pragma unroll
            for (int j = 0; j < 8; ++j) {
                float2 v = unpack2(ca[j]);
                o0 += v.x;
                o1 += v.y;
            }
            float2 hw = *(const float2*)&g_q2[sc_b * 2048 + 1024 + u0];
            o0 += hw.x;
            o1 += hw.y;
            *(float2*)&g_attn_all[((size_t)sc_b * 256 + t) * 1024 + u0] =
                make_float2(o0, o1);
            g_xat[u0 * 64 + sc_b] = o0;
            g_xat[(u0 + 1) * 64 + sc_b] = o1;
        }
        // prefetch next step's Z weight chunk 0 before the barrier (invariant)
        {
            const float* wsrc = g_Wz + (size_t)1024 * 4096 + bid * 32;
#pragma unroll
            for (int i = 0; i < 4; ++i) {
                int f = i * 256 + tid;
                int kk = f >> 3, j = f & 7;
                CPA16P(wbu + f * 16, wsrc + (size_t)kk * 4096 + j * 4, epol);
            }
            CPC();
        }
        gsync(bid);
    }
}

// ---------------- launch: mega at idx 3 (ncu capture slot) ------------------
extern "C" void kernel_launch(void* const* d_in, const int* in_sizes, int n_in,
                              void* d_out, int out_size)
{
    const float* memory  = (const float*)d_in[0];
    const float* dec     = (const float*)d_in[1];
    const float* h0      = (const float*)d_in[2];
    const float* c0      = (const float*)d_in[3];
    const float* W_lstm  = (const float*)d_in[4];
    const float* U_lstm  = (const float*)d_in[5];
    const float* b_lstm  = (const float*)d_in[6];
    const float* W_mem   = (const float*)d_in[7];
    const float* W_query = (const float*)d_in[8];
    const float* v_att   = (const float*)d_in[9];
    const float* W_attn  = (const float*)d_in[10];
    const float* W_out   = (const float*)d_in[11];
    const float* b_out   = (const float*)d_in[12];
    const int*   mem_len = (const int*)d_in[13];
    float* out = (float*)d_out;

    void* p;
    cudaGetSymbolAddress(&p, g_keys);     float* keys = (float*)p;
    cudaGetSymbolAddress(&p, g_MW);       float* MW = (float*)p;
    cudaGetSymbolAddress(&p, g_attn_all); float* attn_all = (float*)p;
    cudaGetSymbolAddress(&p, g_Zx);       float* Zx = (float*)p;

    static int smem_set = 0;
    if (!smem_set) {
        cudaFuncSetAttribute(mega, cudaFuncAttributeMaxDynamicSharedMemorySize,
                             SMEM_BYTES);
        smem_set = 1;
    }

    // 0: Zx = dec @ W_lstm[:1024] + b_lstm, gate-interleaved via perm epilogue
    gemm_tf32<<<dim3(64, 128), 256>>>(dec, W_lstm, b_lstm, Zx,
                                      16384, 4096, 1024, 1);
    // 1: keys = memory @ W_mem
    gemm_tf32<<<dim3(16, 128), 256>>>(memory, W_mem, nullptr, keys,
                                      16384, 1024, 1024, 0);
    // 2: MW = memory @ W_attn[1024:, :]
    gemm_tf32<<<dim3(16, 128), 256>>>(memory, W_attn + 1024 * 1024, nullptr, MW,
                                      16384, 1024, 1024, 0);
    // 3: all 256 decoder steps (weight reorder folded into init) — PROFILED
    mega<<<NBLK, 256, SMEM_BYTES>>>(h0, c0, W_lstm, U_lstm, W_query, W_attn,
                                    v_att, mem_len);
    // 4: out = attn_all @ W_out + b_out
    gemm_tf32<<<dim3(16, 128), 256>>>(attn_all, W_out, b_out, out,
                                      16384, 1024, 1024, 0);
}

// round 12
// speedup vs baseline: 1.0890x; 1.0890x over previous
#include <cuda_runtime.h>
#include <cstdint>

typedef unsigned long long ull;

#define NBLK 128
#define NTHR 512

// ---------------- scratch (no mallocs allowed) ----------------
__device__ float g_keys[64 * 256 * 1024];             // memory @ W_mem          64MB
__device__ float g_MW[64 * 256 * 1024];               // memory @ W_attn[1024:]  64MB
__device__ float g_attn_all[(size_t)64 * 256 * 1024]; // attn outputs            64MB
__device__ float g_Wz[(size_t)3072 * 4096];           // gate-interleaved [Wl;Ul] 48MB
__device__ float g_Zx[(size_t)64 * 256 * 4096];       // dec @ Wz_top + bias    256MB
__device__ float g_xat[1024 * 64];                    // attn transposed [u][b]
__device__ float g_hT[2][1024 * 64];                  // h transposed, double buffered
__device__ float g_c[64 * 1024];
__device__ float g_q2[64 * 2048];                     // [q | h@Wa_top]
__device__ float g_scores[64 * 256];
__device__ unsigned g_cntg[8 * 32];                   // padded group counters
__device__ unsigned g_cntr;                           // root counter
__device__ volatile unsigned g_gen;
__device__ unsigned g_pcnt[64];
__device__ volatile unsigned g_pgen[64];

// ---------------- helpers ----------------
__device__ __forceinline__ ull pack2dup(float x) {
    ull r;
    asm("mov.b64 %0, {%1, %1};" : "=l"(r) : "f"(x));
    return r;
}
__device__ __forceinline__ float2 unpack2(ull v) {
    float2 r;
    asm("mov.b64 {%0, %1}, %2;" : "=f"(r.x), "=f"(r.y) : "l"(v));
    return r;
}
__device__ __forceinline__ void fma2(ull& acc, ull a, ull b) {
    asm("fma.rn.f32x2 %0, %1, %2, %0;" : "+l"(acc) : "l"(a), "l"(b));
}
__device__ __forceinline__ ull add2(ull a, ull b) {
    ull r;
    asm("add.rn.f32x2 %0, %1, %2;" : "=l"(r) : "l"(a), "l"(b));
    return r;
}
__device__ __forceinline__ float tanh_ap(float x) {
    float y;
    asm("tanh.approx.f32 %0, %1;" : "=f"(y) : "f"(x));
    return y;
}
__device__ __forceinline__ float sigf(float x) { return 1.0f / (1.0f + __expf(-x)); }

__device__ __forceinline__ unsigned sptr(const void* p) {
    return (unsigned)__cvta_generic_to_shared(p);
}
__device__ __forceinline__ unsigned f2tf32(float f) {
    unsigned u;
    asm("cvt.rna.tf32.f32 %0, %1;" : "=r"(u) : "f"(f));
    return u;
}
#define CPA16(d, s) asm volatile("cp.async.cg.shared.global [%0], [%1], 16;" :: "r"(d), "l"(s))
#define CPA16P(d, s, pol) \
    asm volatile("cp.async.cg.shared.global.L2::cache_hint [%0], [%1], 16, %2;" \
                 :: "r"(d), "l"(s), "l"(pol))
#define CPC()       asm volatile("cp.async.commit_group;")
#define CPW(n)      asm volatile("cp.async.wait_group %0;" :: "n"(n))

__device__ __forceinline__ ull evict_first_policy() {
    ull p;
    asm("createpolicy.fractional.L2::evict_first.b64 %0, 1.0;" : "=l"(p));
    return p;
}

// ---------------- software grid barrier (2-level arrival, monotonic) --------
__device__ __forceinline__ void gsync(int bid) {
    __syncthreads();
    if (threadIdx.x == 0) {
        unsigned g = g_gen;
        __threadfence();
        int grp = (bid >> 4) * 32;
        if ((atomicAdd(&g_cntg[grp], 1u) & 15u) == 15u) {
            if ((atomicAdd(&g_cntr, 1u) & 7u) == 7u) {
                __threadfence();
                g_gen = g + 1;
            }
        }
        if (g_gen == g) {
            do { __nanosleep(32); } while (g_gen == g);
        }
        __threadfence();
    }
    __syncthreads();
}

// ---------------- block-pair barrier (blocks 2p, 2p+1), monotonic ----------
__device__ __forceinline__ void psync(int pair) {
    __syncthreads();
    if (threadIdx.x == 0) {
        unsigned g = g_pgen[pair];
        __threadfence();
        if (atomicAdd(&g_pcnt[pair], 1u) & 1u) {
            __threadfence();
            g_pgen[pair] = g + 1;
        } else {
            while (g_pgen[pair] == g) {}
        }
        __threadfence();
    }
    __syncthreads();
}

// ---------------- tf32 tensor-core GEMM: C[M,N] = A[M,K]@B[K,N] (+bias) -----
// block tile 128x64, BK=32; 8 warps of 64x16; M%128==0, N%64==0, K%32==0
// perm!=0: write column n to n' = (n&1023)*4 + (n>>10)  (gate interleave)
__global__ __launch_bounds__(256, 2) void gemm_tf32(
    const float* __restrict__ A, const float* __restrict__ Bm,
    const float* __restrict__ bias, float* __restrict__ C, int M, int N, int K,
    int perm)
{
    __shared__ __align__(16) unsigned As[32][136];  // [k][m] tf32 bits
    __shared__ __align__(16) unsigned Bs[32][72];   // [k][n]

    const int tid = threadIdx.x;
    const int w = tid >> 5, lane = tid & 31;
    const int g = lane >> 2, tg = lane & 3;
    const int wm = (w & 1) * 64, wn = (w >> 1) * 16;

    const int m_a = tid >> 1;
    const int ka0 = (tid & 1) * 16;
    const int k_b = tid >> 3;
    const int n_b = (tid & 7) * 8;

    const float* Ap = A + (size_t)(blockIdx.y * 128 + m_a) * K + ka0;
    const float* Bp = Bm + (size_t)k_b * N + blockIdx.x * 64 + n_b;

    float acc[4][2][4];
#pragma unroll
    for (int mt = 0; mt < 4; ++mt)
#pragma unroll
        for (int nt = 0; nt < 2; ++nt)
#pragma unroll
            for (int i = 0; i < 4; ++i) acc[mt][nt][i] = 0.f;

    float4 ra[4], rb[2];
#pragma unroll
    for (int e = 0; e < 4; ++e) ra[e] = *(const float4*)(Ap + e * 4);
    rb[0] = *(const float4*)(Bp);
    rb[1] = *(const float4*)(Bp + 4);

    for (int k0 = 0; k0 < K; k0 += 32) {
        if (k0) __syncthreads();
#pragma unroll
        for (int e = 0; e < 4; ++e) {
            As[ka0 + e * 4 + 0][m_a] = f2tf32(ra[e].x);
            As[ka0 + e * 4 + 1][m_a] = f2tf32(ra[e].y);
            As[ka0 + e * 4 + 2][m_a] = f2tf32(ra[e].z);
            As[ka0 + e * 4 + 3][m_a] = f2tf32(ra[e].w);
        }
#pragma unroll
        for (int e = 0; e < 2; ++e) {
            uint4 t;
            t.x = f2tf32(rb[e].x);
            t.y = f2tf32(rb[e].y);
            t.z = f2tf32(rb[e].z);
            t.w = f2tf32(rb[e].w);
            *(uint4*)&Bs[k_b][n_b + e * 4] = t;
        }
        __syncthreads();
        if (k0 + 32 < K) {
#pragma unroll
            for (int e = 0; e < 4; ++e)
                ra[e] = *(const float4*)(Ap + k0 + 32 + e * 4);
            rb[0] = *(const float4*)(Bp + (size_t)(k0 + 32) * N);
            rb[1] = *(const float4*)(Bp + (size_t)(k0 + 32) * N + 4);
        }
#pragma unroll
        for (int ks = 0; ks < 4; ++ks) {
            const int kk = ks * 8;
            unsigned af[4][4], bf[2][2];
#pragma unroll
            for (int mt = 0; mt < 4; ++mt) {
                int mb = wm + mt * 16 + g;
                af[mt][0] = As[kk + tg][mb];
                af[mt][1] = As[kk + tg][mb + 8];
                af[mt][2] = As[kk + tg + 4][mb];
                af[mt][3] = As[kk + tg + 4][mb + 8];
            }
#pragma unroll
            for (int nt = 0; nt < 2; ++nt) {
                int nb = wn + nt * 8 + g;
                bf[nt][0] = Bs[kk + tg][nb];
                bf[nt][1] = Bs[kk + tg + 4][nb];
            }
#pragma unroll
            for (int mt = 0; mt < 4; ++mt)
#pragma unroll
                for (int nt = 0; nt < 2; ++nt) {
                    asm volatile(
                        "mma.sync.aligned.m16n8k8.row.col.f32.tf32.tf32.f32 "
                        "{%0,%1,%2,%3}, {%4,%5,%6,%7}, {%8,%9}, {%0,%1,%2,%3};"
                        : "+f"(acc[mt][nt][0]), "+f"(acc[mt][nt][1]),
                          "+f"(acc[mt][nt][2]), "+f"(acc[mt][nt][3])
                        : "r"(af[mt][0]), "r"(af[mt][1]), "r"(af[mt][2]),
                          "r"(af[mt][3]), "r"(bf[nt][0]), "r"(bf[nt][1]));
                }
        }
    }

#pragma unroll
    for (int mt = 0; mt < 4; ++mt) {
#pragma unroll
        for (int nt = 0; nt < 2; ++nt) {
            int m = blockIdx.y * 128 + wm + mt * 16 + g;
            int n = blockIdx.x * 64 + wn + nt * 8 + 2 * tg;
            float c0 = acc[mt][nt][0], c1 = acc[mt][nt][1];
            float c2 = acc[mt][nt][2], c3 = acc[mt][nt][3];
            if (bias) {
                float b0 = bias[n], b1 = bias[n + 1];
                c0 += b0; c1 += b1; c2 += b0; c3 += b1;
            }
            if (perm) {
                int np0 = (n & 1023) * 4 + (n >> 10);
                int np1 = ((n + 1) & 1023) * 4 + ((n + 1) >> 10);
                C[(size_t)m * N + np0] = c0;
                C[(size_t)m * N + np1] = c1;
                C[(size_t)(m + 8) * N + np0] = c2;
                C[(size_t)(m + 8) * N + np1] = c3;
            } else {
                *(float2*)(C + (size_t)m * N + n) = make_float2(c0, c1);
                *(float2*)(C + (size_t)(m + 8) * N + n) = make_float2(c2, c3);
            }
        }
    }
}

// ---------------- persistent megakernel: all 256 decoder steps ----------------
// dynamic smem (floats):
//  actb[2][8192] wb[2][4096] zs[8448 ull = 16896 fl] qv[1024] vv[1024] red[256] ps[256]
#define SMEM_FLOATS (16384 + 8192 + 16896 + 1024 + 1024 + 256 + 256)
#define SMEM_BYTES  (SMEM_FLOATS * 4)

__global__ __launch_bounds__(NTHR, 1) void mega(
    const float* __restrict__ h0, const float* __restrict__ c0,
    const float* __restrict__ Wl, const float* __restrict__ Ul,
    const float* __restrict__ Wq, const float* __restrict__ Wa,
    const float* __restrict__ va, const int* __restrict__ mlen)
{
    extern __shared__ __align__(16) float smem[];
    float* actb = smem;               // 2 x 8192
    float* wb   = smem + 16384;       // 2 x 4096
    ull*   zs   = (ull*)(smem + 24576);   // 8 regions x 32 x 33 ull
    float* qv   = smem + 24576 + 16896;
    float* vv   = qv + 1024;
    float* red  = vv + 1024;
    float* ps   = red + 256;

    const int tid = threadIdx.x, bid = blockIdx.x;
    const int w = tid >> 5, lane = tid & 31;
    const unsigned actbu = sptr(actb), wbu = sptr(wb);
    const ull epol = evict_first_policy();

    // init: weight reorder W'[k][u*4+g] = [Wl;Ul][k][g*1024+u]
    for (size_t idx = (size_t)bid * NTHR + tid; idx < (size_t)3072 * 4096;
         idx += (size_t)NBLK * NTHR) {
        int k = (int)(idx >> 12), cp = (int)(idx & 4095);
        int u = cp >> 2, gg = cp & 3;
        g_Wz[idx] = (k < 2048) ? Wl[(size_t)k * 4096 + gg * 1024 + u]
                               : Ul[(size_t)(k - 2048) * 4096 + gg * 1024 + u];
    }
    // init state (transposed)
    for (int i = bid * NTHR + tid; i < 64 * 1024; i += NBLK * NTHR) {
        int b = i >> 10, u = i & 1023;
        g_hT[1][u * 64 + b] = h0[i];
        g_c[i] = c0[i];
        g_xat[u * 64 + b] = 0.f;   // attn_0 = 0
    }
    for (int i = tid; i < 1024; i += NTHR) vv[i] = va[i];

    // role constants
    const int q_cg = bid >> 1, q_bh = bid & 1;
    const float* q_wb = (q_cg < 32) ? (Wq + q_cg * 32 + lane)
                                    : (Wa + (q_cg - 32) * 32 + lane);
    const int sc_b = bid >> 1;
    const int sc_half = bid & 1;
    const int s_len = mlen[sc_b];

    gsync(bid);

    // prefetch Z weight chunk 0 (step-invariant)
    {
        const float* wsrc = g_Wz + (size_t)1024 * 4096 + bid * 32;
#pragma unroll
        for (int i = 0; i < 2; ++i) {
            int f = i * NTHR + tid;
            int kk = f >> 3, j = f & 7;
            CPA16P(wbu + f * 16, wsrc + (size_t)kk * 4096 + j * 4, epol);
        }
        CPC();
    }

    for (int t = 0; t < 256; ++t) {
        const float* hTprev = g_hT[(t & 1) ^ 1];
        float* hTcur = g_hT[t & 1];

        // ===== Z: z = Zx[t] + [attn|h] @ Wz_bot ============================
        // hoist Zx epilogue load (depends only on t); one output per thread
        const int ze_b = tid >> 3, ze_u = tid & 7;
        float4 zxr = __ldcs((const float4*)(
            g_Zx + ((size_t)ze_b * 256 + t) * 4096 + (bid * 8 + ze_u) * 4));

        ull acc[32];
#pragma unroll
        for (int p = 0; p < 32; ++p) acc[p] = 0ull;

        // stage act chunk 0 (weights chunk 0 already committed pre-barrier)
        {
            const float* asrc = g_xat;
#pragma unroll
            for (int i = 0; i < 4; ++i) {
                int f = i * NTHR + tid;
                CPA16(actbu + f * 16, asrc + f * 4);
            }
            CPC();
        }
        for (int c = 0; c < 16; ++c) {
            int cb = c & 1;
            if (c < 15) {
                int cn = c + 1, nb = cb ^ 1;
                const float* asrc = (cn < 8) ? (g_xat + cn * 8192)
                                             : (hTprev + (cn - 8) * 8192);
                unsigned au = actbu + nb * 32768;
#pragma unroll
                for (int i = 0; i < 4; ++i) {
                    int f = i * NTHR + tid;
                    CPA16(au + f * 16, asrc + f * 4);
                }
                const float* wsrc =
                    g_Wz + (size_t)(1024 + cn * 128) * 4096 + bid * 32;
                unsigned wu = wbu + nb * 16384;
#pragma unroll
                for (int i = 0; i < 2; ++i) {
                    int f = i * NTHR + tid;
                    int kk = f >> 3, j = f & 7;
                    CPA16P(wu + f * 16, wsrc + (size_t)kk * 4096 + j * 4, epol);
                }
                CPC();
                CPW(1);
            } else {
                CPW(0);
            }
            __syncthreads();
            const float* ab = actb + cb * 8192;
            const float* wp = wb + cb * 4096;
#pragma unroll
            for (int kk = 0; kk < 8; ++kk) {
                int k = w * 8 + kk;
                ull wv = pack2dup(wp[k * 32 + lane]);
                const ulonglong2* ar = (const ulonglong2*)(ab + k * 64);
#pragma unroll
                for (int p = 0; p < 16; ++p) {
                    ulonglong2 a2 = ar[p];
                    fma2(acc[2 * p], wv, a2.x);
                    fma2(acc[2 * p + 1], wv, a2.y);
                }
            }
            __syncthreads();
        }
        // tree-reduce 16 warps -> warp0
#define ZST(r)                                                            \
        { _Pragma("unroll") for (int p = 0; p < 32; ++p)                  \
            zs[((r) * 32 + lane) * 33 + p] = acc[p]; }
#define ZAD(r)                                                            \
        { _Pragma("unroll") for (int p = 0; p < 32; ++p)                  \
            acc[p] = add2(acc[p], zs[((r) * 32 + lane) * 33 + p]); }
        if (w >= 8) ZST(w - 8);
        __syncthreads();
        if (w < 8) ZAD(w);
        __syncthreads();
        if (w >= 4 && w < 8) ZST(w - 4);
        __syncthreads();
        if (w < 4) ZAD(w);
        __syncthreads();
        if (w == 2 || w == 3) ZST(w - 2);
        __syncthreads();
        if (w < 2) ZAD(w);
        __syncthreads();
        if (w == 1) ZST(0);
        __syncthreads();
        if (w == 0) { ZAD(0); ZST(0); }
        __syncthreads();
        // gate epilogue: one (b, u) per thread
        {
            int b = ze_b, ul = ze_u;
            float z0 = ((const float*)(zs + (ul * 4 + 0) * 33))[b] + zxr.x;
            float z1 = ((const float*)(zs + (ul * 4 + 1) * 33))[b] + zxr.y;
            float z2 = ((const float*)(zs + (ul * 4 + 2) * 33))[b] + zxr.z;
            float z3 = ((const float*)(zs + (ul * 4 + 3) * 33))[b] + zxr.w;
            float ig = sigf(z0), fg = sigf(z1);
            float gg = tanhf(z2), og = sigf(z3);
            int ci = b * 1024 + bid * 8 + ul;
            float cc = fg * g_c[ci] + ig * gg;
            g_c[ci] = cc;
            hTcur[(bid * 8 + ul) * 64 + b] = og * tanhf(cc);
        }
        gsync(bid);

        // ===== Q: [q | h@Wa_top] = h @ [Wq | Wa_top] (staged, 4 chunks) ====
        ull qa[16];
#pragma unroll
        for (int p = 0; p < 16; ++p) qa[p] = 0ull;
        {
#pragma unroll
            for (int i = 0; i < 4; ++i) {
                int f = i * NTHR + tid;
                int kl = f >> 3, bc = f & 7;
                CPA16(actbu + f * 16,
                      hTcur + ((size_t)kl * 64 + q_bh * 32 + bc * 4));
            }
            CPC();
        }
        for (int c = 0; c < 4; ++c) {
            int cb = c & 1;
            if (c < 3) {
                int cn = c + 1, nb = cb ^ 1;
                unsigned au = actbu + nb * 32768;
#pragma unroll
                for (int i = 0; i < 4; ++i) {
                    int f = i * NTHR + tid;
                    int kl = f >> 3, bc = f & 7;
                    CPA16(au + f * 16,
                          hTcur + ((size_t)(cn * 256 + kl) * 64 + q_bh * 32 + bc * 4));
                }
                CPC();
                CPW(1);
            } else {
                CPW(0);
            }
            __syncthreads();
            const float* hb = actb + cb * 8192;
#pragma unroll
            for (int g = 0; g < 2; ++g) {
                float wr[8];
                const float* wpg = q_wb + (size_t)(c * 256 + w * 16 + g * 8) * 1024;
#pragma unroll
                for (int kk = 0; kk < 8; ++kk) wr[kk] = wpg[(size_t)kk * 1024];
#pragma unroll
                for (int kk = 0; kk < 8; ++kk) {
                    ull wv = pack2dup(wr[kk]);
                    const ulonglong2* ar =
                        (const ulonglong2*)(hb + (w * 16 + g * 8 + kk) * 32);
#pragma unroll
                    for (int p = 0; p < 8; ++p) {
                        ulonglong2 a2 = ar[p];
                        fma2(qa[2 * p], wv, a2.x);
                        fma2(qa[2 * p + 1], wv, a2.y);
                    }
                }
            }
            __syncthreads();
        }
#define QST(r)                                                            \
        { _Pragma("unroll") for (int p = 0; p < 16; ++p)                  \
            zs[((r) * 32 + lane) * 33 + p] = qa[p]; }
#define QAD(r)                                                            \
        { _Pragma("unroll") for (int p = 0; p < 16; ++p)                  \
            qa[p] = add2(qa[p], zs[((r) * 32 + lane) * 33 + p]); }
        if (w >= 8) QST(w - 8);
        __syncthreads();
        if (w < 8) QAD(w);
        __syncthreads();
        if (w >= 4 && w < 8) QST(w - 4);
        __syncthreads();
        if (w < 4) QAD(w);
        __syncthreads();
        if (w == 2 || w == 3) QST(w - 2);
        __syncthreads();
        if (w < 2) QAD(w);
        __syncthreads();
        if (w == 1) QST(0);
        __syncthreads();
        if (w == 0) {
            QAD(0);
            int n = q_cg * 32 + lane;
#pragma unroll
            for (int p = 0; p < 16; ++p) {
                float2 v = unpack2(qa[p]);
                g_q2[(q_bh * 32 + 2 * p) * 2048 + n] = v.x;
                g_q2[(q_bh * 32 + 2 * p + 1) * 2048 + n] = v.y;
            }
        }
        gsync(bid);

        // ===== S: masked additive scores (16 warps x 8 rows) ===============
        if (tid < 256)
            *(float4*)&qv[tid * 4] = *(const float4*)&g_q2[sc_b * 2048 + tid * 4];
        __syncthreads();
#pragma unroll
        for (int i = 0; i < 8; ++i) {
            int s = sc_half * 128 + w * 8 + i;
            float sv = -1e9f;
            if (s < s_len) {
                const float* kp = g_keys + ((size_t)sc_b * 256 + s) * 1024;
                float a = 0.f;
#pragma unroll
                for (int j = 0; j < 8; ++j) {
                    int u = lane * 4 + j * 128;
                    float4 kv = *(const float4*)(kp + u);
                    float4 qf = *(const float4*)(qv + u);
                    float4 vf = *(const float4*)(vv + u);
                    a += tanh_ap(kv.x + qf.x) * vf.x + tanh_ap(kv.y + qf.y) * vf.y
                       + tanh_ap(kv.z + qf.z) * vf.z + tanh_ap(kv.w + qf.w) * vf.w;
                }
#pragma unroll
                for (int off = 16; off; off >>= 1)
                    a += __shfl_xor_sync(0xffffffffu, a, off);
                sv = a;
            }
            if (lane == 0) g_scores[sc_b * 256 + s] = sv;
        }
        psync(sc_b);

        // ===== C: softmax + align@MW + hWa -> attn (1 u per thread) ========
        {
            float mys = (tid < 256) ? g_scores[sc_b * 256 + tid] : -1e9f;
            if (tid < 256) red[tid] = mys;
            __syncthreads();
            for (int st = 128; st; st >>= 1) {
                if (tid < st) red[tid] = fmaxf(red[tid], red[tid + st]);
                __syncthreads();
            }
            float m = red[0];
            __syncthreads();
            float e = __expf(mys - m);   // masked rows underflow to exactly 0
            if (tid < 256) red[tid] = e;
            __syncthreads();
            for (int st = 128; st; st >>= 1) {
                if (tid < st) red[tid] += red[tid + st];
                __syncthreads();
            }
            float inv = 1.f / red[0];
            __syncthreads();
            if (tid < 256) ps[tid] = e * inv;
            __syncthreads();

            int len8 = (s_len + 7) & ~7;
            int u0 = sc_half * 512 + tid;
            const float* mwp = g_MW + (size_t)sc_b * 256 * 1024 + u0;
            float ca[8];
#pragma unroll
            for (int p = 0; p < 8; ++p) ca[p] = 0.f;
            for (int s = 0; s < len8; s += 8) {
#pragma unroll
                for (int j = 0; j < 8; ++j)
                    ca[j] += ps[s + j] * mwp[(size_t)(s + j) * 1024];
            }
            float o = ((ca[0] + ca[1]) + (ca[2] + ca[3])) +
                      ((ca[4] + ca[5]) + (ca[6] + ca[7]));
            o += g_q2[sc_b * 2048 + 1024 + u0];
            g_attn_all[((size_t)sc_b * 256 + t) * 1024 + u0] = o;
            g_xat[u0 * 64 + sc_b] = o;
        }
        // prefetch next step's Z weight chunk 0 before the barrier (invariant)
        {
            const float* wsrc = g_Wz + (size_t)1024 * 4096 + bid * 32;
#pragma unroll
            for (int i = 0; i < 2; ++i) {
                int f = i * NTHR + tid;
                int kk = f >> 3, j = f & 7;
                CPA16P(wbu + f * 16, wsrc + (size_t)kk * 4096 + j * 4, epol);
            }
            CPC();
        }
        gsync(bid);
    }
}

// ---------------- launch: mega at idx 3 (ncu capture slot) ------------------
extern "C" void kernel_launch(void* const* d_in, const int* in_sizes, int n_in,
                              void* d_out, int out_size)
{
    const float* memory  = (const float*)d_in[0];
    const float* dec     = (const float*)d_in[1];
    const float* h0      = (const float*)d_in[2];
    const float* c0      = (const float*)d_in[3];
    const float* W_lstm  = (const float*)d_in[4];
    const float* U_lstm  = (const float*)d_in[5];
    const float* b_lstm  = (const float*)d_in[6];
    const float* W_mem   = (const float*)d_in[7];
    const float* W_query = (const float*)d_in[8];
    const float* v_att   = (const float*)d_in[9];
    const float* W_attn  = (const float*)d_in[10];
    const float* W_out   = (const float*)d_in[11];
    const float* b_out   = (const float*)d_in[12];
    const int*   mem_len = (const int*)d_in[13];
    float* out = (float*)d_out;

    void* p;
    cudaGetSymbolAddress(&p, g_keys);     float* keys = (float*)p;
    cudaGetSymbolAddress(&p, g_MW);       float* MW = (float*)p;
    cudaGetSymbolAddress(&p, g_attn_all); float* attn_all = (float*)p;
    cudaGetSymbolAddress(&p, g_Zx);       float* Zx = (float*)p;

    static int smem_set = 0;
    if (!smem_set) {
        cudaFuncSetAttribute(mega, cudaFuncAttributeMaxDynamicSharedMemorySize,
                             SMEM_BYTES);
        smem_set = 1;
    }

    // 0: Zx = dec @ W_lstm[:1024] + b_lstm, gate-interleaved via perm epilogue
    gemm_tf32<<<dim3(64, 128), 256>>>(dec, W_lstm, b_lstm, Zx,
                                      16384, 4096, 1024, 1);
    // 1: keys = memory @ W_mem
    gemm_tf32<<<dim3(16, 128), 256>>>(memory, W_mem, nullptr, keys,
                                      16384, 1024, 1024, 0);
    // 2: MW = memory @ W_attn[1024:, :]
    gemm_tf32<<<dim3(16, 128), 256>>>(memory, W_attn + 1024 * 1024, nullptr, MW,
                                      16384, 1024, 1024, 0);
    // 3: all 256 decoder steps (512 threads / 16 warps per SM) — PROFILED
    mega<<<NBLK, NTHR, SMEM_BYTES>>>(h0, c0, W_lstm, U_lstm, W_query, W_attn,
                                     v_att, mem_len);
    // 4: out = attn_all @ W_out + b_out
    gemm_tf32<<<dim3(16, 128), 256>>>(attn_all, W_out, b_out, out,
                                      16384, 1024, 1024, 0);
}